// round 17
// baseline (speedup 1.0000x reference)
#include <cuda_runtime.h>
#include <cuda_fp16.h>
#include <cstdint>
#include <math.h>

#define NT      2048
#define DMODEL  2048
#define NHEAD   16
#define DHEAD   128
#define INNERD  2048
#define FFI     8192
#define VOCAB   32000
#define NLAYER  4
#define EPSF    1e-5f
#define MASKV   1e-10f
#define BSTRN   136    // [k][n] smem stride (elems) for NN B tiles
#define L2E     1.4426950408889634f
#define PSCALE  1024.0f
#define PISCALE 9.765625e-4f

typedef __half f16;

// ---------------- scratch (static device globals; no allocations) ----------------
__device__ float g_x [NT * DMODEL];
__device__ f16   g_hh[NT * DMODEL], g_hl[NT * DMODEL];
__device__ f16   g_qh[NT * INNERD], g_ql[NT * INNERD];
__device__ float g_kv [NT * 256];
__device__ f16   g_kvh[NT * 256], g_kvl[NT * 256];      // K pair cols 0-127; V pair cols 128-255
__device__ float g_suf[NT * DHEAD];
__device__ float g_c  [NHEAD * NT];
__device__ float g_S [(size_t)NHEAD * NT * NT];
__device__ f16   g_Ph[(size_t)NHEAD * NT * NT];          // P single (hi only)
__device__ f16   g_aoh[NT * INNERD];                     // ao single
__device__ f16   g_f1h[NT * FFI];                        // f1 single
// weights
__device__ f16 w_qh [NLAYER * DMODEL * INNERD], w_ql [NLAYER * DMODEL * INNERD];
__device__ f16 w_kvh[NLAYER * DMODEL * 256],    w_kvl[NLAYER * DMODEL * 256];
__device__ f16 w_oh [NLAYER * INNERD * DMODEL], w_ol [NLAYER * INNERD * DMODEL];
__device__ f16 w_igh[(size_t)NLAYER * DMODEL * 2 * FFI];   // wi|wg column-interleaved, single
__device__ f16 w_foh[(size_t)NLAYER * FFI * DMODEL], w_fol[(size_t)NLAYER * FFI * DMODEL];
__device__ f16 w_eh [(size_t)VOCAB * DMODEL];

// ---------------- helpers ----------------
__device__ __forceinline__ void cpa16(uint32_t dst, const void* src) {
    asm volatile("cp.async.cg.shared.global [%0],[%1],16;" :: "r"(dst), "l"(src));
}
__device__ __forceinline__ void ldsm4(uint32_t* r, uint32_t a) {
    asm volatile("ldmatrix.sync.aligned.m8n8.x4.shared.b16 {%0,%1,%2,%3},[%4];"
                 : "=r"(r[0]), "=r"(r[1]), "=r"(r[2]), "=r"(r[3]) : "r"(a));
}
__device__ __forceinline__ void ldsm4t(uint32_t* r, uint32_t a) {
    asm volatile("ldmatrix.sync.aligned.m8n8.x4.trans.shared.b16 {%0,%1,%2,%3},[%4];"
                 : "=r"(r[0]), "=r"(r[1]), "=r"(r[2]), "=r"(r[3]) : "r"(a));
}
__device__ __forceinline__ void mma16816(float* c, const uint32_t* a, uint32_t b0, uint32_t b1) {
    asm volatile("mma.sync.aligned.m16n8k16.row.col.f32.f16.f16.f32 "
                 "{%0,%1,%2,%3},{%4,%5,%6,%7},{%8,%9},{%0,%1,%2,%3};"
                 : "+f"(c[0]), "+f"(c[1]), "+f"(c[2]), "+f"(c[3])
                 : "r"(a[0]), "r"(a[1]), "r"(a[2]), "r"(a[3]), "r"(b0), "r"(b1));
}
__device__ __forceinline__ void split1(float a, f16& h, f16& l) {
    h = __float2half_rn(a);
    l = __float2half_rn(a - __half2float(h));
}
__device__ __forceinline__ void split2_store(f16* hp, f16* lp, float a, float b) {
    f16 ha = __float2half_rn(a), hb = __float2half_rn(b);
    f16 la = __float2half_rn(a - __half2float(ha));
    f16 lb = __float2half_rn(b - __half2float(hb));
    __half2 H = __halves2half2(ha, hb);
    __half2 L = __halves2half2(la, lb);
    *(uint32_t*)hp = *(uint32_t*)&H;
    *(uint32_t*)lp = *(uint32_t*)&L;
}
__device__ __forceinline__ float silu_mul(float a, float g) {
    return a * g / (1.f + __expf(-g));
}

// ---------------- fp32 -> fp16 pair ----------------
__global__ void __launch_bounds__(256) cvt_pair_kernel(const float* __restrict__ in,
                                                       f16* __restrict__ ho, f16* __restrict__ lo) {
    size_t i = (size_t)blockIdx.x * 256 + threadIdx.x;
    float4 v = ((const float4*)in)[i];
    f16 h0, l0, h1, l1, h2, l2, h3, l3;
    split1(v.x, h0, l0); split1(v.y, h1, l1); split1(v.z, h2, l2); split1(v.w, h3, l3);
    __half2 ha = __halves2half2(h0, h1), hb = __halves2half2(h2, h3);
    __half2 la = __halves2half2(l0, l1), lb = __halves2half2(l2, l3);
    uint2 H = {*(uint32_t*)&ha, *(uint32_t*)&hb};
    uint2 L = {*(uint32_t*)&la, *(uint32_t*)&lb};
    ((uint2*)ho)[i] = H;
    ((uint2*)lo)[i] = L;
}

// ---------------- fp32 -> fp16 single ----------------
__global__ void __launch_bounds__(256) cvt_half_kernel(const float* __restrict__ in,
                                                       f16* __restrict__ out) {
    size_t i = (size_t)blockIdx.x * 256 + threadIdx.x;
    float4 v = ((const float4*)in)[i];
    __half2 a = __floats2half2_rn(v.x, v.y);
    __half2 b = __floats2half2_rn(v.z, v.w);
    uint2 o = {*(uint32_t*)&a, *(uint32_t*)&b};
    ((uint2*)out)[i] = o;
}

// ---- interleave cvt: out[d][2j]=a[d][j], out[d][2j+1]=b[d][j] ----
__global__ void __launch_bounds__(256) cvt_ilv_kernel(const float* __restrict__ a,
                                                      const float* __restrict__ b,
                                                      f16* __restrict__ out) {
    size_t i = (size_t)blockIdx.x * 256 + threadIdx.x;
    float2 va = ((const float2*)a)[i];
    float2 vb = ((const float2*)b)[i];
    __half2 p0 = __floats2half2_rn(va.x, vb.x);
    __half2 p1 = __floats2half2_rn(va.y, vb.y);
    uint2 o = {*(uint32_t*)&p0, *(uint32_t*)&p1};
    ((uint2*)out)[i] = o;
}

// ---- strided pair cvt: in [R,128] -> out [R,256] at column offset ----
__global__ void __launch_bounds__(256) cvt_pair_cols_kernel(const float* __restrict__ in,
                                                            f16* __restrict__ ho, f16* __restrict__ lo,
                                                            int colOff) {
    size_t i = (size_t)blockIdx.x * 256 + threadIdx.x;
    int row = (int)(i >> 5);
    int col = ((int)i & 31) * 4;
    float4 v = ((const float4*)in)[i];
    size_t o = (size_t)row * 256 + colOff + col;
    f16 h0, l0, h1, l1, h2, l2, h3, l3;
    split1(v.x, h0, l0); split1(v.y, h1, l1); split1(v.z, h2, l2); split1(v.w, h3, l3);
    __half2 ha = __halves2half2(h0, h1), hb = __halves2half2(h2, h3);
    __half2 la = __halves2half2(l0, l1), lb = __halves2half2(l2, l3);
    *(uint32_t*)(ho + o)     = *(uint32_t*)&ha;
    *(uint32_t*)(ho + o + 2) = *(uint32_t*)&hb;
    *(uint32_t*)(lo + o)     = *(uint32_t*)&la;
    *(uint32_t*)(lo + o + 2) = *(uint32_t*)&lb;
}

// ---------------- embedding ----------------
__global__ void embed_kernel(const int* __restrict__ tok, const float* __restrict__ emb,
                             float* __restrict__ x) {
    int n = blockIdx.x;
    const float* src = emb + (size_t)tok[n] * DMODEL;
    float* dst = x + (size_t)n * DMODEL;
    for (int d = threadIdx.x; d < DMODEL; d += blockDim.x) dst[d] = src[d];
}

// ---------------- RMSNorm -> fp16 pair ----------------
__global__ void __launch_bounds__(256) rmsnorm_pair_kernel(const float* __restrict__ x,
                                                           const float* __restrict__ gamma,
                                                           f16* __restrict__ oh, f16* __restrict__ ol) {
    int n = blockIdx.x;
    const float* row = x + (size_t)n * DMODEL;
    float s = 0.f;
    for (int d = threadIdx.x; d < DMODEL; d += 256) { float v = row[d]; s += v * v; }
    __shared__ float red[256];
    red[threadIdx.x] = s; __syncthreads();
    #pragma unroll
    for (int k = 128; k > 0; k >>= 1) {
        if (threadIdx.x < k) red[threadIdx.x] += red[threadIdx.x + k];
        __syncthreads();
    }
    float inv = rsqrtf(red[0] * (1.0f / DMODEL) + EPSF);
    for (int d = threadIdx.x; d < DMODEL; d += 256) {
        f16 h, l; split1(row[d] * inv * gamma[d], h, l);
        oh[(size_t)n * DMODEL + d] = h;
        ol[(size_t)n * DMODEL + d] = l;
    }
}

// ---------------- suffixV ----------------
__global__ void __launch_bounds__(128) suffixv_kernel(const float* __restrict__ kv,
                                                      float* __restrict__ suf) {
    const int d = threadIdx.x;
    const int lo = blockIdx.x * 128, hi = lo + 128;
    float acc = 0.f;
    for (int j = NT - 1; j >= hi; --j)
        acc += kv[(size_t)j * 256 + 128 + d];
    for (int i = hi - 1; i >= lo; --i) {
        suf[(size_t)i * DHEAD + d] = acc;
        acc += kv[(size_t)i * 256 + 128 + d];
    }
}

// ------- softmax: visible exact, masked rank-1; P single (hi), scaled x1024 -------
__global__ void __launch_bounds__(256) softmax_kernel(const float* __restrict__ S,
                                                      f16* __restrict__ Ph,
                                                      float* __restrict__ C) {
    const int i = blockIdx.x, h = blockIdx.y, tid = threadIdx.x;
    const float* row = S + ((size_t)h * NT + i) * NT;
    __shared__ float sc[NT];
    __shared__ float red[256];
    const float slope = exp2f(-0.5f * (float)(h + 1));
    const float scale = 0.08838834764831845f;
    const int tileEnd = ((i >> 7) + 1) << 7;

    float mx = MASKV;
    for (int j = tid; j <= i; j += 256) {
        float v = row[j] * scale + slope * (float)j;
        sc[j] = v;
        mx = fmaxf(mx, v);
    }
    red[tid] = mx; __syncthreads();
    #pragma unroll
    for (int s = 128; s > 0; s >>= 1) {
        if (tid < s) red[tid] = fmaxf(red[tid], red[tid + s]);
        __syncthreads();
    }
    mx = red[0]; __syncthreads();

    float sum = 0.f;
    for (int j = tid; j <= i; j += 256) {
        float p = exp2f((sc[j] - mx) * L2E);
        sc[j] = p; sum += p;
    }
    red[tid] = sum; __syncthreads();
    #pragma unroll
    for (int s = 128; s > 0; s >>= 1) {
        if (tid < s) red[tid] += red[tid + s];
        __syncthreads();
    }
    const float maskexp = exp2f((MASKV - mx) * L2E);
    const float inv = 1.f / (red[0] + (float)(NT - 1 - i) * maskexp);
    const float c = maskexp * inv;
    if (tid == 0) C[(size_t)h * NT + i] = c;

    const float pw = inv * PSCALE;
    f16* ph = Ph + ((size_t)h * NT + i) * NT;
    for (int j = tid; j < tileEnd; j += 256)
        ph[j] = __float2half_rn(j <= i ? sc[j] * pw : 0.f);
}

// ================= pipelined fp16-split tensor-core GEMM =================
// Passes: aH x bH always; + aH x bL if BPAIR; + aL x bH if APAIR.
// KTT: k-tile depth. EPI: 0 fp32, 1 fp32 +=, 2 atomicAdd, 3 pair store,
//      4 fused attn-out single, 6 fused SwiGLU single on interleaved wi|wg.
// CAUSAL: 0 none; 1 skip tiles colBase>rowBase; 2 cap K at rowBase+128.
// SWAPXY: blockIdx.x indexes M tiles (wave covers all M of few N cols -> B L2 reuse).
template <int TRANSB, int EPI, int CAUSAL, int APAIR, int BPAIR, int KTT, int SWAPXY>
__global__ void __launch_bounds__(256, 2)
gemm_hs(const f16* __restrict__ Ah, const f16* __restrict__ Al,
        const f16* __restrict__ Bh, const f16* __restrict__ Bl,
        float* __restrict__ C, f16* __restrict__ Ch, f16* __restrict__ Cl,
        const float* __restrict__ Xa, const float* __restrict__ Xb,
        int M, int N, int K, int lda, int ldb, int ldc,
        int kSplit, size_t aZ, size_t bZ, size_t cZ) {
    extern __shared__ __align__(16) char smem[];
    const int tid = threadIdx.x, lane = tid & 31, warp = tid >> 5;
    const int wm = warp >> 2, wn = warp & 3;
    const int rowBase = (SWAPXY ? blockIdx.x : blockIdx.y) * 128;
    const int colBase = (SWAPXY ? blockIdx.y : blockIdx.x) * 128;
    if (CAUSAL == 1 && colBase > rowBase) return;
    const int z = blockIdx.z;
    int kStart = 0, kEnd = K;
    if (CAUSAL == 2) kEnd = rowBase + 128 < K ? rowBase + 128 : K;
    if (kSplit > 1) {
        int kl = K / kSplit; kStart = z * kl; kEnd = kStart + kl;
    } else {
        Ah += z * aZ; if (APAIR) Al += z * aZ;
        Bh += z * bZ; if (BPAIR) Bl += z * bZ;
        if (EPI == 3 || EPI == 4 || EPI == 6) { Ch += z * cZ; if (EPI == 3) Cl += z * cZ; }
        else { C += z * cZ; }
    }
    const int nk = (kEnd - kStart) / KTT;
    const uint32_t sb = (uint32_t)__cvta_generic_to_shared(smem);
    constexpr int ASTRT  = KTT + 8;
    constexpr int AHALF  = 128 * ASTRT * 2;
    constexpr int ASTAGE = (1 + APAIR) * AHALF;
    constexpr int BUFB   = TRANSB ? 128 * ASTRT * 2 : KTT * BSTRN * 2;
    constexpr int BSTAGE = (1 + BPAIR) * BUFB;
    constexpr int NLD    = KTT / 16;

    auto load_stage = [&](int s, int kt) {
        uint32_t aOff = sb + s * ASTAGE;
        uint32_t bOff = sb + 2 * ASTAGE + s * BSTAGE;
        #pragma unroll
        for (int r = 0; r < NLD; ++r) {
            int idx = tid + r * 256;
            int row = idx / (KTT / 8), kc = (idx % (KTT / 8)) * 8;
            uint32_t d = aOff + (row * ASTRT + kc) * 2;
            const size_t ga = (size_t)(rowBase + row) * lda + kt + kc;
            cpa16(d, Ah + ga);
            if (APAIR) cpa16(d + AHALF, Al + ga);
            if (!TRANSB) {
                int kr = idx >> 4, nc = (idx & 15) * 8;
                uint32_t db = bOff + (kr * BSTRN + nc) * 2;
                const size_t gb = (size_t)(kt + kr) * ldb + colBase + nc;
                cpa16(db, Bh + gb);
                if (BPAIR) cpa16(db + BUFB, Bl + gb);
            } else {
                int nr = idx / (KTT / 8), kc2 = (idx % (KTT / 8)) * 8;
                uint32_t db = bOff + (nr * ASTRT + kc2) * 2;
                const size_t gb = (size_t)(colBase + nr) * ldb + kt + kc2;
                cpa16(db, Bh + gb);
                if (BPAIR) cpa16(db + BUFB, Bl + gb);
            }
        }
        asm volatile("cp.async.commit_group;");
    };

    float acc[4][4][4];
    #pragma unroll
    for (int i = 0; i < 4; ++i)
        #pragma unroll
        for (int j = 0; j < 4; ++j)
            #pragma unroll
            for (int v = 0; v < 4; ++v) acc[i][j][v] = 0.f;

    const int l15 = lane & 15, lhi = (lane >> 4) * 8;

    load_stage(0, kStart);

    for (int it = 0; it < nk; ++it) {
        const int s = it & 1;
        if (it + 1 < nk) {
            load_stage((it + 1) & 1, kStart + (it + 1) * KTT);
            asm volatile("cp.async.wait_group 1;");
        } else {
            asm volatile("cp.async.wait_group 0;");
        }
        __syncthreads();

        const uint32_t aBase = sb + s * ASTAGE + ((wm * 64 + l15) * ASTRT + lhi) * 2;
        const uint32_t bOff  = sb + 2 * ASTAGE + s * BSTAGE;

        #pragma unroll
        for (int ks = 0; ks < KTT; ks += 16) {
            uint32_t aH[4][4], aL[4][4], bH[2][4], bL[2][4];
            #pragma unroll
            for (int mt = 0; mt < 4; ++mt)
                ldsm4(aH[mt], aBase + ks * 2 + mt * (16 * ASTRT * 2));
            if (!TRANSB) {
                uint32_t bBase = bOff + ((l15 + ks) * BSTRN + wn * 32 + lhi) * 2;
                #pragma unroll
                for (int p = 0; p < 2; ++p) ldsm4t(bH[p], bBase + p * 32);
            } else {
                #pragma unroll
                for (int p = 0; p < 2; ++p)
                    ldsm4(bH[p], bOff + ((wn * 32 + p * 16 + l15) * ASTRT + ks + lhi) * 2);
            }
            #pragma unroll
            for (int mt = 0; mt < 4; ++mt)
                #pragma unroll
                for (int nt = 0; nt < 4; ++nt) {
                    int p = nt >> 1, su = nt & 1;
                    uint32_t b0 = TRANSB ? bH[p][su]     : bH[p][2 * su];
                    uint32_t b1 = TRANSB ? bH[p][su + 2] : bH[p][2 * su + 1];
                    mma16816(acc[mt][nt], aH[mt], b0, b1);
                }
            if (BPAIR) {
                if (!TRANSB) {
                    uint32_t bBase = bOff + BUFB + ((l15 + ks) * BSTRN + wn * 32 + lhi) * 2;
                    #pragma unroll
                    for (int p = 0; p < 2; ++p) ldsm4t(bL[p], bBase + p * 32);
                } else {
                    #pragma unroll
                    for (int p = 0; p < 2; ++p)
                        ldsm4(bL[p], bOff + BUFB + ((wn * 32 + p * 16 + l15) * ASTRT + ks + lhi) * 2);
                }
                #pragma unroll
                for (int mt = 0; mt < 4; ++mt)
                    #pragma unroll
                    for (int nt = 0; nt < 4; ++nt) {
                        int p = nt >> 1, su = nt & 1;
                        uint32_t b0 = TRANSB ? bL[p][su]     : bL[p][2 * su];
                        uint32_t b1 = TRANSB ? bL[p][su + 2] : bL[p][2 * su + 1];
                        mma16816(acc[mt][nt], aH[mt], b0, b1);
                    }
            }
            if (APAIR) {
                #pragma unroll
                for (int mt = 0; mt < 4; ++mt)
                    ldsm4(aL[mt], aBase + AHALF + ks * 2 + mt * (16 * ASTRT * 2));
                #pragma unroll
                for (int mt = 0; mt < 4; ++mt)
                    #pragma unroll
                    for (int nt = 0; nt < 4; ++nt) {
                        int p = nt >> 1, su = nt & 1;
                        uint32_t b0 = TRANSB ? bH[p][su]     : bH[p][2 * su];
                        uint32_t b1 = TRANSB ? bH[p][su + 2] : bH[p][2 * su + 1];
                        mma16816(acc[mt][nt], aL[mt], b0, b1);
                    }
            }
        }
        __syncthreads();
    }

    // ---------- epilogue ----------
    const int r0 = rowBase + wm * 64 + (lane >> 2);
    const int c0 = colBase + wn * 32 + (lane & 3) * 2;
    #pragma unroll
    for (int mt = 0; mt < 4; ++mt) {
        #pragma unroll
        for (int nt = 0; nt < 4; ++nt) {
            int r = r0 + mt * 16, c = c0 + nt * 8;
            if (EPI == 6) {
                int j = c >> 1;
                Ch[(size_t)r * ldc + j]       = __float2half_rn(silu_mul(acc[mt][nt][0], acc[mt][nt][1]));
                Ch[(size_t)(r + 8) * ldc + j] = __float2half_rn(silu_mul(acc[mt][nt][2], acc[mt][nt][3]));
            } else if (EPI == 4) {
                float ca = Xa[(size_t)z * NT + r];
                float cb = Xa[(size_t)z * NT + r + 8];
                float v0 = acc[mt][nt][0] * PISCALE + ca * Xb[(size_t)r * DHEAD + c];
                float v1 = acc[mt][nt][1] * PISCALE + ca * Xb[(size_t)r * DHEAD + c + 1];
                float v2 = acc[mt][nt][2] * PISCALE + cb * Xb[(size_t)(r + 8) * DHEAD + c];
                float v3 = acc[mt][nt][3] * PISCALE + cb * Xb[(size_t)(r + 8) * DHEAD + c + 1];
                __half2 H0 = __floats2half2_rn(v0, v1);
                __half2 H1 = __floats2half2_rn(v2, v3);
                *(uint32_t*)(Ch + (size_t)r * ldc + c)       = *(uint32_t*)&H0;
                *(uint32_t*)(Ch + (size_t)(r + 8) * ldc + c) = *(uint32_t*)&H1;
            } else if (EPI == 3) {
                split2_store(Ch + (size_t)r * ldc + c,       Cl + (size_t)r * ldc + c,
                             acc[mt][nt][0], acc[mt][nt][1]);
                split2_store(Ch + (size_t)(r + 8) * ldc + c, Cl + (size_t)(r + 8) * ldc + c,
                             acc[mt][nt][2], acc[mt][nt][3]);
            } else if (EPI == 2) {
                atomicAdd(C + (size_t)r * ldc + c,           acc[mt][nt][0]);
                atomicAdd(C + (size_t)r * ldc + c + 1,       acc[mt][nt][1]);
                atomicAdd(C + (size_t)(r + 8) * ldc + c,     acc[mt][nt][2]);
                atomicAdd(C + (size_t)(r + 8) * ldc + c + 1, acc[mt][nt][3]);
            } else {
                float2* p0 = (float2*)(C + (size_t)r * ldc + c);
                float2* p1 = (float2*)(C + (size_t)(r + 8) * ldc + c);
                if (EPI == 1) {
                    float2 t0 = *p0, t1 = *p1;
                    t0.x += acc[mt][nt][0]; t0.y += acc[mt][nt][1];
                    t1.x += acc[mt][nt][2]; t1.y += acc[mt][nt][3];
                    *p0 = t0; *p1 = t1;
                } else {
                    *p0 = make_float2(acc[mt][nt][0], acc[mt][nt][1]);
                    *p1 = make_float2(acc[mt][nt][2], acc[mt][nt][3]);
                }
            }
        }
    }
}

// ---------------- host-side dispatch ----------------
template <int TRANSB, int EPI, int CAUSAL, int APAIR, int BPAIR, int KTT, int SWAPXY = 0>
static void launch_gemm(const f16* Ah, const f16* Al, const f16* Bh, const f16* Bl,
                        float* C, f16* Ch, f16* Cl,
                        const float* Xa, const float* Xb,
                        int M, int N, int K, int lda, int ldb, int ldc,
                        int Z, int kSplit, size_t aZ, size_t bZ, size_t cZ) {
    const int astrt  = KTT + 8;
    const int ahalf  = 128 * astrt * 2;
    const int bufb   = TRANSB ? 128 * astrt * 2 : KTT * BSTRN * 2;
    const int smem   = 2 * (1 + APAIR) * ahalf + 2 * (1 + BPAIR) * bufb;
    cudaFuncSetAttribute(gemm_hs<TRANSB, EPI, CAUSAL, APAIR, BPAIR, KTT, SWAPXY>,
                         cudaFuncAttributeMaxDynamicSharedMemorySize, smem);
    dim3 grid(SWAPXY ? M / 128 : N / 128, SWAPXY ? N / 128 : M / 128, Z);
    gemm_hs<TRANSB, EPI, CAUSAL, APAIR, BPAIR, KTT, SWAPXY><<<grid, 256, smem>>>(
        Ah, Al, Bh, Bl, C, Ch, Cl, Xa, Xb, M, N, K, lda, ldb, ldc, kSplit, aZ, bZ, cZ);
}

extern "C" void kernel_launch(void* const* d_in, const int* in_sizes, int n_in,
                              void* d_out, int out_size) {
    const int*   tokens      = (const int*)  d_in[0];
    const float* emb         = (const float*)d_in[1];
    const float* attn_gamma  = (const float*)d_in[2];
    const float* wq          = (const float*)d_in[3];
    const float* wk          = (const float*)d_in[4];
    const float* wv          = (const float*)d_in[5];
    const float* wo          = (const float*)d_in[6];
    const float* ff_gamma    = (const float*)d_in[7];
    const float* wi          = (const float*)d_in[8];
    const float* wg          = (const float*)d_in[9];
    const float* wfo         = (const float*)d_in[10];
    const float* final_gamma = (const float*)d_in[11];
    float* out = (float*)d_out;

    float *x, *kv, *suf, *c, *S;
    f16 *hh, *hl, *qh, *ql, *kvh, *kvl, *Ph, *aoh, *f1h;
    f16 *Wqh, *Wql, *Wkvh, *Wkvl, *Woh, *Wol, *Wigh, *Wfoh, *Wfol, *Weh;
    cudaGetSymbolAddress((void**)&x,    g_x);
    cudaGetSymbolAddress((void**)&hh,   g_hh);  cudaGetSymbolAddress((void**)&hl,  g_hl);
    cudaGetSymbolAddress((void**)&qh,   g_qh);  cudaGetSymbolAddress((void**)&ql,  g_ql);
    cudaGetSymbolAddress((void**)&kv,   g_kv);
    cudaGetSymbolAddress((void**)&kvh,  g_kvh); cudaGetSymbolAddress((void**)&kvl, g_kvl);
    cudaGetSymbolAddress((void**)&suf,  g_suf); cudaGetSymbolAddress((void**)&c,   g_c);
    cudaGetSymbolAddress((void**)&S,    g_S);
    cudaGetSymbolAddress((void**)&Ph,   g_Ph);
    cudaGetSymbolAddress((void**)&aoh,  g_aoh);
    cudaGetSymbolAddress((void**)&f1h,  g_f1h);
    cudaGetSymbolAddress((void**)&Wqh,  w_qh);  cudaGetSymbolAddress((void**)&Wql, w_ql);
    cudaGetSymbolAddress((void**)&Wkvh, w_kvh); cudaGetSymbolAddress((void**)&Wkvl, w_kvl);
    cudaGetSymbolAddress((void**)&Woh,  w_oh);  cudaGetSymbolAddress((void**)&Wol, w_ol);
    cudaGetSymbolAddress((void**)&Wigh, w_igh);
    cudaGetSymbolAddress((void**)&Wfoh, w_foh); cudaGetSymbolAddress((void**)&Wfol, w_fol);
    cudaGetSymbolAddress((void**)&Weh,  w_eh);

    auto cvtp = [](const float* in, f16* h, f16* l, size_t n) {
        cvt_pair_kernel<<<(unsigned)(n / 1024), 256>>>(in, h, l);
    };
    auto cvts = [](const float* in, f16* h, size_t n) {
        cvt_half_kernel<<<(unsigned)(n / 1024), 256>>>(in, h);
    };

    // ---- weight pre-split (captured; runs each replay) ----
    cvtp(wq,  Wqh,  Wql,  (size_t)NLAYER * DMODEL * INNERD);
    cvtp(wo,  Woh,  Wol,  (size_t)NLAYER * INNERD * DMODEL);
    cvtp(wfo, Wfoh, Wfol, (size_t)NLAYER * FFI * DMODEL);
    cvts(emb, Weh,  (size_t)VOCAB * DMODEL);
    for (int l = 0; l < NLAYER; ++l) {
        const size_t okv  = (size_t)l * DMODEL * DHEAD;
        const size_t okvW = (size_t)l * DMODEL * 256;
        const size_t oig  = (size_t)l * DMODEL * FFI;
        cvt_pair_cols_kernel<<<(DMODEL * DHEAD) / 1024, 256>>>(wk + okv, Wkvh + okvW, Wkvl + okvW, 0);
        cvt_pair_cols_kernel<<<(DMODEL * DHEAD) / 1024, 256>>>(wv + okv, Wkvh + okvW, Wkvl + okvW, 128);
        cvt_ilv_kernel<<<(unsigned)((size_t)DMODEL * FFI / 512), 256>>>(
            wi + oig, wg + oig, Wigh + 2 * oig);
    }

    embed_kernel<<<NT, 256>>>(tokens, emb, x);

    for (int l = 0; l < NLAYER; ++l) {
        const size_t oq   = (size_t)l * DMODEL * INNERD;
        const size_t okvW = (size_t)l * DMODEL * 256;
        const size_t oig  = (size_t)l * DMODEL * 2 * FFI;
        const size_t ofo  = (size_t)l * FFI * DMODEL;

        // --- attention ---
        rmsnorm_pair_kernel<<<NT, 256>>>(x, attn_gamma + (size_t)l * DMODEL, hh, hl);
        // q projection: full 3-pass -> q pair
        launch_gemm<0, 3, 0, 1, 1, 32>(hh, hl, Wqh + oq, Wql + oq, nullptr, qh, ql, nullptr, nullptr,
                                       NT, INNERD, DMODEL, DMODEL, INNERD, INNERD, 1, 1, 0, 0, 0);
        cudaMemsetAsync(kv, 0, NT * 256 * sizeof(float));
        // kv projection: full 3-pass, split-K 8
        launch_gemm<0, 2, 0, 1, 1, 32>(hh, hl, Wkvh + okvW, Wkvl + okvW, kv, nullptr, nullptr, nullptr, nullptr,
                                       NT, 256, DMODEL, DMODEL, 256, 256, 8, 8, 0, 0, 0);
        cvtp(kv, kvh, kvl, (size_t)NT * 256);
        suffixv_kernel<<<NT / 128, 128>>>(kv, suf);
        // S = Q K^T: 3-pass, causal-skip upper tiles
        launch_gemm<1, 0, 1, 1, 1, 32>(qh, ql, kvh, kvl, S, nullptr, nullptr, nullptr, nullptr,
                                       NT, NT, DHEAD, INNERD, 256, NT,
                                       NHEAD, 1, (size_t)DHEAD, 0, (size_t)NT * NT);
        softmax_kernel<<<dim3(NT, NHEAD), 256>>>(S, Ph, c);
        // PV: P single x V pair, K capped at diagonal, fused ao-fix -> aoh single
        launch_gemm<0, 4, 2, 0, 1, 64>(Ph, nullptr, kvh + 128, kvl + 128, nullptr, aoh, nullptr, c, suf,
                                       NT, DHEAD, NT, NT, 256, INNERD,
                                       NHEAD, 1, (size_t)NT * NT, 0, (size_t)DHEAD);
        // output projection: ao single x wo pair, accumulate into x
        launch_gemm<0, 1, 0, 0, 1, 64>(aoh, nullptr, Woh + oq, Wol + oq, x, nullptr, nullptr, nullptr, nullptr,
                                       NT, DMODEL, INNERD, INNERD, DMODEL, DMODEL, 1, 1, 0, 0, 0);

        // --- SwiGLU FFN: interleaved wi|wg GEMM (h pair x w single), SWAPXY raster ---
        rmsnorm_pair_kernel<<<NT, 256>>>(x, ff_gamma + (size_t)l * DMODEL, hh, hl);
        launch_gemm<0, 6, 0, 1, 0, 64, 1>(hh, hl, Wigh + oig, nullptr, nullptr, f1h, nullptr, nullptr, nullptr,
                                          NT, 2 * FFI, DMODEL, DMODEL, 2 * FFI, FFI, 1, 1, 0, 0, 0);
        // down projection: f1 single x wfo pair, accumulate into x
        launch_gemm<0, 1, 0, 0, 1, 64>(f1h, nullptr, Wfoh + ofo, Wfol + ofo, x, nullptr, nullptr, nullptr, nullptr,
                                       NT, DMODEL, FFI, FFI, DMODEL, DMODEL, 1, 1, 0, 0, 0);
    }

    // --- final norm + tied-embedding logits: h pair x emb single, TN, SWAPXY raster ---
    rmsnorm_pair_kernel<<<NT, 256>>>(x, final_gamma, hh, hl);
    launch_gemm<1, 0, 0, 1, 0, 64, 1>(hh, hl, Weh, nullptr, out, nullptr, nullptr, nullptr, nullptr,
                                      NT, VOCAB, DMODEL, DMODEL, DMODEL, VOCAB, 1, 1, 0, 0, 0);
}